// round 10
// baseline (speedup 1.0000x reference)
#include <cuda_runtime.h>
#include <cuda_fp16.h>
#include <cstdint>

// Problem constants (fixed by the dataset)
#define B_    8
#define V_    12288
#define E_    98304
#define FIN_  256
#define FOUT_ 256
#define KCH_  4
#define BF_   (B_*FIN_)    // 2048 floats per node row
#define ROWS_ (B_*V_)      // 98304 output rows

// ---------------- scratch (device globals: no runtime allocation) ----------
// Self-cleaning invariant: g_cnt, g_sum, g_sq are zero at module load and are
// returned to zero by the end of every kernel_launch call.
__device__ float g_T1[(size_t)V_*BF_];
__device__ float g_T2[(size_t)V_*BF_];
__device__ float g_T3[(size_t)V_*BF_];
__device__ int   g_rowptr[V_+1];
__device__ int   g_cursor[V_];
__device__ int   g_cnt[V_];
__device__ int   g_col[E_];
__device__ float g_w[E_];
__device__ float g_sum[FOUT_], g_sq[FOUT_];
__device__ float g_scale[FOUT_], g_shift[FOUT_];

// ---------------- CSR build (R6-proven) --------------------------------------
__global__ void k_hist(const int* __restrict__ dst) {
    int e = blockIdx.x*blockDim.x + threadIdx.x;
    if (e < E_) atomicAdd(&g_cnt[dst[e]], 1);
}

__global__ void k_scan() {
    __shared__ int sh[1024];
    int t = threadIdx.x;
    int base = t*12;
    int loc[12];
    int s = 0;
    #pragma unroll
    for (int i = 0; i < 12; ++i) { loc[i] = s; s += g_cnt[base+i]; }
    sh[t] = s;
    __syncthreads();
    for (int off = 1; off < 1024; off <<= 1) {
        int v = 0;
        if (t >= off) v = sh[t-off];
        __syncthreads();
        if (t >= off) sh[t] += v;
        __syncthreads();
    }
    int pre = (t == 0) ? 0 : sh[t-1];
    #pragma unroll
    for (int i = 0; i < 12; ++i) {
        int p = pre + loc[i];
        g_rowptr[base+i] = p;
        g_cursor[base+i] = p;
    }
    if (t == 1023) g_rowptr[V_] = sh[1023];
}

__global__ void k_scatter(const int* __restrict__ src, const int* __restrict__ dst,
                          const float* __restrict__ ew) {
    int e = blockIdx.x*blockDim.x + threadIdx.x;
    if (e < E_) {
        int d = dst[e];
        int p = atomicAdd(&g_cursor[d], 1);
        g_col[p] = src[e];
        g_w[p]   = ew[e];
        atomicSub(&g_cnt[d], 1);   // self-clean for next call
    }
}

// ---------------- SpMM: Chebyshev recursion (R6-proven) ----------------------
__device__ __forceinline__ void fma4(float4& acc, float wt, const float4& t) {
    acc.x = fmaf(wt, t.x, acc.x);
    acc.y = fmaf(wt, t.y, acc.y);
    acc.z = fmaf(wt, t.z, acc.z);
    acc.w = fmaf(wt, t.w, acc.w);
}

__global__ __launch_bounds__(256) void k_spmm(const float* __restrict__ x, int stage) {
    const float* y;  const float* p2 = nullptr;  float* o;
    long ys, ps = 0;
    const int v  = blockIdx.x;
    const int j0 = (blockIdx.y << 10) + threadIdx.x*4;
    const long xo = (long)(j0>>8)*((long)V_*FIN_) + (j0&255);
    long yo, po = 0;
    if (stage == 1)      { y = x;    ys = FIN_; yo = xo; o = g_T1; }
    else if (stage == 2) { y = g_T1; ys = BF_;  yo = j0;
                           p2 = x;   ps = FIN_; po = xo; o = g_T2; }
    else                 { y = g_T2; ys = BF_;  yo = j0;
                           p2 = g_T1; ps = BF_; po = j0; o = g_T3; }

    int r0 = g_rowptr[v], r1 = g_rowptr[v+1];
    float4 a0 = make_float4(0,0,0,0);

    int e = r0;
    #pragma unroll 1
    for (; e + 4 <= r1; e += 4) {
        int   s0 = __ldg(&g_col[e]),   s1 = __ldg(&g_col[e+1]);
        int   s2 = __ldg(&g_col[e+2]), s3 = __ldg(&g_col[e+3]);
        float w0 = __ldg(&g_w[e]),     w1 = __ldg(&g_w[e+1]);
        float w2 = __ldg(&g_w[e+2]),   w3 = __ldg(&g_w[e+3]);
        float4 t0 = *(const float4*)(y + yo + (long)s0*ys);
        float4 t1 = *(const float4*)(y + yo + (long)s1*ys);
        float4 t2 = *(const float4*)(y + yo + (long)s2*ys);
        float4 t3 = *(const float4*)(y + yo + (long)s3*ys);
        fma4(a0, w0, t0);
        fma4(a0, w1, t1);
        fma4(a0, w2, t2);
        fma4(a0, w3, t3);
    }
    #pragma unroll 1
    for (; e < r1; ++e) {
        int   s0 = __ldg(&g_col[e]);
        float w0 = __ldg(&g_w[e]);
        float4 t0 = *(const float4*)(y + yo + (long)s0*ys);
        fma4(a0, w0, t0);
    }
    if (p2) {
        float4 t0 = *(const float4*)(p2 + po + (long)v*ps);
        a0.x = 2.f*a0.x - t0.x; a0.y = 2.f*a0.y - t0.y;
        a0.z = 2.f*a0.z - t0.z; a0.w = 2.f*a0.w - t0.w;
    }
    *(float4*)(o + (long)v*BF_ + j0) = a0;
}

// ---------------- FP16 tensor-core GEMM (m16n8k16, fused BN stats) ----------
// out[b,v,o] = sum_p sum_i A_p(v,b,i) * W[p,i,o]
// fp16 inputs (rn from f32), fp32 accumulate.
// 512 threads: BM=128, BN=256 (A read from HBM exactly once), BK=32.
// 16 warps/SM (4/SMSP) for HMMA-pipe latency hiding; per-warp tile 32x64
// with the R9-proven fragment indexing.
// Bias omitted: constant per-channel shift cancels through BN mean subtraction.
#define BM 128
#define BN 256
#define BK 32
#define NCH (KCH_ * FIN_ / BK)   // 32 chunks

// dynamic smem layout (uint32 half2 words)
#define AS_W   (BM + 4)                       // 132
#define BS_W   (BN + 8)                       // 264
#define AS_OFF 0
#define BS_OFF (2*16*AS_W)                    // 4224 words
#define SS_OFF (BS_OFF + 2*16*BS_W)           // + 8448 words
#define SQ_OFF (SS_OFF + BN)
#define GSMEM_WORDS (SQ_OFF + BN)             // 13440 words = 53760 B

__device__ __forceinline__ uint32_t h2u(__half2 h) {
    return *reinterpret_cast<uint32_t*>(&h);
}

__global__ __launch_bounds__(512) void k_gemm(const float* __restrict__ x,
                                              const float* __restrict__ w,
                                              float* __restrict__ out) {
    extern __shared__ uint32_t smw[];
    uint32_t* As = smw + AS_OFF;              // [2][16][AS_W]
    uint32_t* Bs = smw + BS_OFF;              // [2][16][BS_W]
    float*    s_s = (float*)(smw + SS_OFF);
    float*    s_q = (float*)(smw + SQ_OFF);

    const int b     = blockIdx.y;
    const int vbase = blockIdx.x * BM;
    const int tid  = threadIdx.x;
    const int lane = tid & 31, warp = tid >> 5;
    const int wm = warp & 3, wn = warp >> 2;   // 4 warps along M, 4 along N
    const int g = lane >> 2, tg = lane & 3;

    if (tid < BN) { s_s[tid] = 0.f; s_q[tid] = 0.f; }

    float acc[2][8][4];
    #pragma unroll
    for (int i = 0; i < 2; ++i)
        #pragma unroll
        for (int j = 0; j < 8; ++j)
            #pragma unroll
            for (int c = 0; c < 4; ++c) acc[i][j][c] = 0.f;

    // prefetch registers (converted to half2)
    uint32_t pa[2][2];      // 2 A items x (h01, h23)
    uint32_t pb[2][4];      // 2 B items x 4 half2

    auto prefetch = [&](int t) {
        const int p  = t >> 3;
        const int kb = (t & 7) * BK;
        const float* ab; long as_;
        if (p == 0)      { ab = x    + (long)b*V_*FIN_; as_ = FIN_; }
        else if (p == 1) { ab = g_T1 + (long)b*FIN_;    as_ = BF_;  }
        else if (p == 2) { ab = g_T2 + (long)b*FIN_;    as_ = BF_;  }
        else             { ab = g_T3 + (long)b*FIN_;    as_ = BF_;  }
        #pragma unroll
        for (int i = 0; i < 2; ++i) {
            int item = tid + i*512;            // 0..1023
            int row = item >> 3, q = item & 7;
            float4 v = *(const float4*)(ab + (long)(vbase+row)*as_ + kb + q*4);
            pa[i][0] = h2u(__floats2half2_rn(v.x, v.y));
            pa[i][1] = h2u(__floats2half2_rn(v.z, v.w));
        }
        const float* wb = w + (long)p*FIN_*FOUT_ + (long)kb*FOUT_;
        #pragma unroll
        for (int i = 0; i < 2; ++i) {
            int item = tid + i*512;            // 0..1023
            int pk = item >> 6, n4 = item & 63;
            float4 v0 = *(const float4*)(wb + (long)(2*pk  )*FOUT_ + n4*4);
            float4 v1 = *(const float4*)(wb + (long)(2*pk+1)*FOUT_ + n4*4);
            pb[i][0] = h2u(__floats2half2_rn(v0.x, v1.x));
            pb[i][1] = h2u(__floats2half2_rn(v0.y, v1.y));
            pb[i][2] = h2u(__floats2half2_rn(v0.z, v1.z));
            pb[i][3] = h2u(__floats2half2_rn(v0.w, v1.w));
        }
    };

    prefetch(0);
    int cur = 0;
    #pragma unroll 1
    for (int t = 0; t < NCH; ++t) {
        uint32_t* Ac = As + cur*(16*AS_W);
        uint32_t* Bc = Bs + cur*(16*BS_W);
        #pragma unroll
        for (int i = 0; i < 2; ++i) {
            int item = tid + i*512;
            int row = item >> 3, q = item & 7;
            Ac[(2*q  )*AS_W + row] = pa[i][0];
            Ac[(2*q+1)*AS_W + row] = pa[i][1];
        }
        #pragma unroll
        for (int i = 0; i < 2; ++i) {
            int item = tid + i*512;
            int pk = item >> 6, n4 = item & 63;
            *(uint4*)&Bc[pk*BS_W + n4*4] =
                make_uint4(pb[i][0], pb[i][1], pb[i][2], pb[i][3]);
        }
        __syncthreads();
        if (t + 1 < NCH) prefetch(t + 1);   // overlap global loads with mma

        #pragma unroll
        for (int kk2 = 0; kk2 < 16; kk2 += 8) {   // two k16 steps
            uint32_t a[2][4];
            #pragma unroll
            for (int mt = 0; mt < 2; ++mt) {
                int mb = wm*32 + mt*16;
                a[mt][0] = Ac[(kk2+tg  )*AS_W + mb+g  ];
                a[mt][1] = Ac[(kk2+tg  )*AS_W + mb+g+8];
                a[mt][2] = Ac[(kk2+tg+4)*AS_W + mb+g  ];
                a[mt][3] = Ac[(kk2+tg+4)*AS_W + mb+g+8];
            }
            #pragma unroll
            for (int nt = 0; nt < 8; ++nt) {
                int nb = wn*64 + nt*8;
                uint32_t b0 = Bc[(kk2+tg  )*BS_W + nb+g];
                uint32_t b1 = Bc[(kk2+tg+4)*BS_W + nb+g];
                #pragma unroll
                for (int mt = 0; mt < 2; ++mt) {
                    asm volatile(
                        "mma.sync.aligned.m16n8k16.row.col.f32.f16.f16.f32 "
                        "{%0,%1,%2,%3}, {%4,%5,%6,%7}, {%8,%9}, {%0,%1,%2,%3};\n"
                        : "+f"(acc[mt][nt][0]), "+f"(acc[mt][nt][1]),
                          "+f"(acc[mt][nt][2]), "+f"(acc[mt][nt][3])
                        : "r"(a[mt][0]), "r"(a[mt][1]),
                          "r"(a[mt][2]), "r"(a[mt][3]),
                          "r"(b0), "r"(b1));
                }
            }
        }
        __syncthreads();
        cur ^= 1;
    }

    // epilogue: write raw (pre-BN) result
    #pragma unroll
    for (int mt = 0; mt < 2; ++mt) {
        int row0 = vbase + wm*32 + mt*16 + g;
        #pragma unroll
        for (int nt = 0; nt < 8; ++nt) {
            int col = wn*64 + nt*8 + tg*2;
            float2* p0 = (float2*)&out[((long)b*V_ + row0    )*FOUT_ + col];
            float2* p1 = (float2*)&out[((long)b*V_ + row0 + 8)*FOUT_ + col];
            *p0 = make_float2(acc[mt][nt][0], acc[mt][nt][1]);
            *p1 = make_float2(acc[mt][nt][2], acc[mt][nt][3]);
        }
    }

    // fused BN stats: per-column sum / sumsq over this block's 128 rows
    #pragma unroll
    for (int nt = 0; nt < 8; ++nt) {
        float s0 = acc[0][nt][0] + acc[0][nt][2] + acc[1][nt][0] + acc[1][nt][2];
        float s1 = acc[0][nt][1] + acc[0][nt][3] + acc[1][nt][1] + acc[1][nt][3];
        float q0 = acc[0][nt][0]*acc[0][nt][0] + acc[0][nt][2]*acc[0][nt][2]
                 + acc[1][nt][0]*acc[1][nt][0] + acc[1][nt][2]*acc[1][nt][2];
        float q1 = acc[0][nt][1]*acc[0][nt][1] + acc[0][nt][3]*acc[0][nt][3]
                 + acc[1][nt][1]*acc[1][nt][1] + acc[1][nt][3]*acc[1][nt][3];
        #pragma unroll
        for (int m = 4; m <= 16; m <<= 1) {
            s0 += __shfl_xor_sync(0xffffffffu, s0, m);
            s1 += __shfl_xor_sync(0xffffffffu, s1, m);
            q0 += __shfl_xor_sync(0xffffffffu, q0, m);
            q1 += __shfl_xor_sync(0xffffffffu, q1, m);
        }
        if (lane < 4) {
            int colr = wn*64 + nt*8 + tg*2;
            atomicAdd(&s_s[colr  ], s0); atomicAdd(&s_q[colr  ], q0);
            atomicAdd(&s_s[colr+1], s1); atomicAdd(&s_q[colr+1], q1);
        }
    }
    __syncthreads();
    if (tid < BN) {
        atomicAdd(&g_sum[tid], s_s[tid]);
        atomicAdd(&g_sq[tid],  s_q[tid]);
    }
}

// ---------------- BatchNorm finalize + apply + ReLU -------------------------
__global__ void k_bnfinal(const float* __restrict__ gamma,
                          const float* __restrict__ beta) {
    int o = threadIdx.x;
    const float n = (float)ROWS_;
    float mean = g_sum[o] / n;
    float var  = g_sq[o] / n - mean*mean;      // biased variance (torch-style)
    float sc   = gamma[o] * rsqrtf(var + 1e-5f);
    g_scale[o] = sc;
    g_shift[o] = beta[o] - mean*sc;
    g_sum[o] = 0.f;                 // self-clean for next call
    g_sq[o]  = 0.f;
}

__global__ __launch_bounds__(256) void k_bnapply(float* __restrict__ out) {
    long i = ((long)blockIdx.x*blockDim.x + threadIdx.x) * 4;
    float4 v = *(float4*)(out + i);
    int o = (int)(i & 255);
    v.x = fmaxf(fmaf(v.x, g_scale[o  ], g_shift[o  ]), 0.f);
    v.y = fmaxf(fmaf(v.y, g_scale[o+1], g_shift[o+1]), 0.f);
    v.z = fmaxf(fmaf(v.z, g_scale[o+2], g_shift[o+2]), 0.f);
    v.w = fmaxf(fmaf(v.w, g_scale[o+3], g_shift[o+3]), 0.f);
    *(float4*)(out + i) = v;
}

// ---------------- launch -----------------------------------------------------
extern "C" void kernel_launch(void* const* d_in, const int* in_sizes, int n_in,
                              void* d_out, int out_size) {
    const float* x     = (const float*)d_in[0];
    const float* ew    = (const float*)d_in[1];
    const float* w     = (const float*)d_in[2];
    const float* bias  = (const float*)d_in[3]; (void)bias; // cancels under BN
    const float* gamma = (const float*)d_in[4];
    const float* beta  = (const float*)d_in[5];
    const int*   esrc  = (const int*)d_in[6];
    const int*   edst  = (const int*)d_in[7];
    float* out = (float*)d_out;
    (void)in_sizes; (void)n_in; (void)out_size;

    cudaFuncSetAttribute(k_gemm, cudaFuncAttributeMaxDynamicSharedMemorySize,
                         GSMEM_WORDS*4);

    // CSR build (g_cnt zero by static init + self-clean)
    k_hist<<<E_/256, 256>>>(edst);
    k_scan<<<1, 1024>>>();
    k_scatter<<<E_/256, 256>>>(esrc, edst, ew);

    // Chebyshev recursion (batch-halved for L2 residency)
    dim3 gs(V_, 2);
    k_spmm<<<gs, 256>>>(x, 1);
    k_spmm<<<gs, 256>>>(x, 2);
    k_spmm<<<gs, 256>>>(x, 3);

    // FP16 tensor-core GEMM -> raw output + fused BN statistics
    dim3 gg(V_/BM, B_);
    k_gemm<<<gg, 512, GSMEM_WORDS*4>>>(x, w, out);

    // BatchNorm finalize + apply + ReLU
    k_bnfinal<<<1, FOUT_>>>(gamma, beta);
    k_bnapply<<<(ROWS_*FOUT_)/4/256, 256>>>(out);
}

// round 11
// speedup vs baseline: 1.1210x; 1.1210x over previous
#include <cuda_runtime.h>
#include <cuda_fp16.h>
#include <cstdint>

// Problem constants (fixed by the dataset)
#define B_    8
#define V_    12288
#define E_    98304
#define FIN_  256
#define FOUT_ 256
#define KCH_  4
#define BF_   (B_*FIN_)    // 2048 floats per node row
#define ROWS_ (B_*V_)      // 98304 output rows

// ---------------- scratch (device globals: no runtime allocation) ----------
// Self-cleaning invariant: g_cnt, g_sum, g_sq are zero at module load and are
// returned to zero by the end of every kernel_launch call.
__device__ float g_T1[(size_t)V_*BF_];
__device__ float g_T2[(size_t)V_*BF_];
__device__ float g_T3[(size_t)V_*BF_];
__device__ int   g_rowptr[V_+1];
__device__ int   g_cursor[V_];
__device__ int   g_cnt[V_];
__device__ int   g_col[E_];
__device__ float g_w[E_];
__device__ float g_sum[FOUT_], g_sq[FOUT_];
__device__ float g_scale[FOUT_], g_shift[FOUT_];

// ---------------- CSR build (R6-proven) --------------------------------------
__global__ void k_hist(const int* __restrict__ dst) {
    int e = blockIdx.x*blockDim.x + threadIdx.x;
    if (e < E_) atomicAdd(&g_cnt[dst[e]], 1);
}

__global__ void k_scan() {
    __shared__ int sh[1024];
    int t = threadIdx.x;
    int base = t*12;
    int loc[12];
    int s = 0;
    #pragma unroll
    for (int i = 0; i < 12; ++i) { loc[i] = s; s += g_cnt[base+i]; }
    sh[t] = s;
    __syncthreads();
    for (int off = 1; off < 1024; off <<= 1) {
        int v = 0;
        if (t >= off) v = sh[t-off];
        __syncthreads();
        if (t >= off) sh[t] += v;
        __syncthreads();
    }
    int pre = (t == 0) ? 0 : sh[t-1];
    #pragma unroll
    for (int i = 0; i < 12; ++i) {
        int p = pre + loc[i];
        g_rowptr[base+i] = p;
        g_cursor[base+i] = p;
    }
    if (t == 1023) g_rowptr[V_] = sh[1023];
}

__global__ void k_scatter(const int* __restrict__ src, const int* __restrict__ dst,
                          const float* __restrict__ ew) {
    int e = blockIdx.x*blockDim.x + threadIdx.x;
    if (e < E_) {
        int d = dst[e];
        int p = atomicAdd(&g_cursor[d], 1);
        g_col[p] = src[e];
        g_w[p]   = ew[e];
        atomicSub(&g_cnt[d], 1);   // self-clean for next call
    }
}

// ---------------- SpMM: Chebyshev recursion (R6-proven) ----------------------
__device__ __forceinline__ void fma4(float4& acc, float wt, const float4& t) {
    acc.x = fmaf(wt, t.x, acc.x);
    acc.y = fmaf(wt, t.y, acc.y);
    acc.z = fmaf(wt, t.z, acc.z);
    acc.w = fmaf(wt, t.w, acc.w);
}

__global__ __launch_bounds__(256) void k_spmm(const float* __restrict__ x, int stage) {
    const float* y;  const float* p2 = nullptr;  float* o;
    long ys, ps = 0;
    const int v  = blockIdx.x;
    const int j0 = (blockIdx.y << 10) + threadIdx.x*4;
    const long xo = (long)(j0>>8)*((long)V_*FIN_) + (j0&255);
    long yo, po = 0;
    if (stage == 1)      { y = x;    ys = FIN_; yo = xo; o = g_T1; }
    else if (stage == 2) { y = g_T1; ys = BF_;  yo = j0;
                           p2 = x;   ps = FIN_; po = xo; o = g_T2; }
    else                 { y = g_T2; ys = BF_;  yo = j0;
                           p2 = g_T1; ps = BF_; po = j0; o = g_T3; }

    int r0 = g_rowptr[v], r1 = g_rowptr[v+1];
    float4 a0 = make_float4(0,0,0,0);

    int e = r0;
    #pragma unroll 1
    for (; e + 4 <= r1; e += 4) {
        int   s0 = __ldg(&g_col[e]),   s1 = __ldg(&g_col[e+1]);
        int   s2 = __ldg(&g_col[e+2]), s3 = __ldg(&g_col[e+3]);
        float w0 = __ldg(&g_w[e]),     w1 = __ldg(&g_w[e+1]);
        float w2 = __ldg(&g_w[e+2]),   w3 = __ldg(&g_w[e+3]);
        float4 t0 = *(const float4*)(y + yo + (long)s0*ys);
        float4 t1 = *(const float4*)(y + yo + (long)s1*ys);
        float4 t2 = *(const float4*)(y + yo + (long)s2*ys);
        float4 t3 = *(const float4*)(y + yo + (long)s3*ys);
        fma4(a0, w0, t0);
        fma4(a0, w1, t1);
        fma4(a0, w2, t2);
        fma4(a0, w3, t3);
    }
    #pragma unroll 1
    for (; e < r1; ++e) {
        int   s0 = __ldg(&g_col[e]);
        float w0 = __ldg(&g_w[e]);
        float4 t0 = *(const float4*)(y + yo + (long)s0*ys);
        fma4(a0, w0, t0);
    }
    if (p2) {
        float4 t0 = *(const float4*)(p2 + po + (long)v*ps);
        a0.x = 2.f*a0.x - t0.x; a0.y = 2.f*a0.y - t0.y;
        a0.z = 2.f*a0.z - t0.z; a0.w = 2.f*a0.w - t0.w;
    }
    *(float4*)(o + (long)v*BF_ + j0) = a0;
}

// ---------------- FP16 tensor-core GEMM (m16n8k16, fragment-order smem) -----
// out[b,v,o] = sum_p sum_i A_p(v,b,i) * W[p,i,o]
// fp16 inputs (rn from f32), fp32 accumulate. 256 threads, BM=64, BN=256
// (A read from HBM exactly once), BK=32, double-buffered, one sync per tile
// (R9-proven structure). NEW: smem tiles stored in mma-fragment order
// [kblock][tile][lane][r] -> A fragment = 1 LDS.128, B fragment pair = 1
// LDS.64 (20 LDS/warp/chunk vs 48 scalar before).
// Word (kp, m): lane=(m&7)*4+(kp&3), r=((kp>>2)&1)*2+((m>>3)&1)  [A, 4 words]
// Word (kp, n): lane=(n&7)*4+(kp&3), r=(kp>>2)&1                 [B, 2 words]
// Bias omitted: constant per-channel shift cancels through BN mean subtraction.
#define BM 64
#define BN 256
#define BK 32
#define NCH (KCH_ * FIN_ / BK)   // 32 chunks

#define ATW 132                   // A tile stride: 32 lanes*4 words + 4 pad
#define BTW 66                    // B tile stride: 32 lanes*2 words + 2 pad
#define ATILES 8                  // 2 kblocks * 4 mtiles (BM/16)
#define BTILES 64                 // 2 kblocks * 32 n8tiles (BN/8)

__device__ __forceinline__ uint32_t h2u(__half2 h) {
    return *reinterpret_cast<uint32_t*>(&h);
}

__global__ __launch_bounds__(256) void k_gemm(const float* __restrict__ x,
                                              const float* __restrict__ w,
                                              float* __restrict__ out) {
    __shared__ uint32_t As[2][ATILES*ATW];    //  8448 B
    __shared__ uint32_t Bs[2][BTILES*BTW];    // 33792 B
    __shared__ float s_s[BN], s_q[BN];        //  2048 B

    const int b     = blockIdx.y;
    const int vbase = blockIdx.x * BM;
    const int tid  = threadIdx.x;
    const int lane = tid & 31, warp = tid >> 5;
    const int wm = warp & 1, wn = warp >> 1;   // 2 warps along M, 4 along N

    s_s[tid] = 0.f; s_q[tid] = 0.f;

    float acc[2][8][4];
    #pragma unroll
    for (int i = 0; i < 2; ++i)
        #pragma unroll
        for (int j = 0; j < 8; ++j)
            #pragma unroll
            for (int c = 0; c < 4; ++c) acc[i][j][c] = 0.f;

    // prefetch registers (converted to half2)
    uint32_t pa[2][2];      // 2 A items x (kp=2q, kp=2q+1)
    uint32_t pb[4][4];      // 4 B items x 4 cols

    auto prefetch = [&](int t) {
        const int p  = t >> 3;
        const int kb = (t & 7) * BK;
        const float* ab; long as_;
        if (p == 0)      { ab = x    + (long)b*V_*FIN_; as_ = FIN_; }
        else if (p == 1) { ab = g_T1 + (long)b*FIN_;    as_ = BF_;  }
        else if (p == 2) { ab = g_T2 + (long)b*FIN_;    as_ = BF_;  }
        else             { ab = g_T3 + (long)b*FIN_;    as_ = BF_;  }
        #pragma unroll
        for (int i = 0; i < 2; ++i) {
            int item = tid + i*256;            // 0..511
            int row = item >> 3, q = item & 7;
            float4 v = *(const float4*)(ab + (long)(vbase+row)*as_ + kb + q*4);
            pa[i][0] = h2u(__floats2half2_rn(v.x, v.y));
            pa[i][1] = h2u(__floats2half2_rn(v.z, v.w));
        }
        const float* wb = w + (long)p*FIN_*FOUT_ + (long)kb*FOUT_;
        #pragma unroll
        for (int i = 0; i < 4; ++i) {
            int item = tid + i*256;            // 0..1023
            int pk = item >> 6, n4 = item & 63;
            float4 v0 = *(const float4*)(wb + (long)(2*pk  )*FOUT_ + n4*4);
            float4 v1 = *(const float4*)(wb + (long)(2*pk+1)*FOUT_ + n4*4);
            pb[i][0] = h2u(__floats2half2_rn(v0.x, v1.x));
            pb[i][1] = h2u(__floats2half2_rn(v0.y, v1.y));
            pb[i][2] = h2u(__floats2half2_rn(v0.z, v1.z));
            pb[i][3] = h2u(__floats2half2_rn(v0.w, v1.w));
        }
    };

    prefetch(0);
    int cur = 0;
    #pragma unroll 1
    for (int t = 0; t < NCH; ++t) {
        uint32_t* Ac = As[cur];
        uint32_t* Bc = Bs[cur];
        // A store: item (row, q) -> words (kp=2q+c, row), c=0,1
        #pragma unroll
        for (int i = 0; i < 2; ++i) {
            int item = tid + i*256;
            int row = item >> 3, q = item & 7;
            int tile = (q >> 2)*4 + (row >> 4);
            int ls   = (row & 7)*4 + (q & 1)*2;
            int r4   = ((q >> 1) & 1)*2 + ((row >> 3) & 1);
            uint32_t base = tile*ATW + r4;
            Ac[base + (ls  )*4] = pa[i][0];
            Ac[base + (ls+1)*4] = pa[i][1];
        }
        // B store: item (pk, n4) -> words (kp=pk, n=4*n4+j), j=0..3
        #pragma unroll
        for (int i = 0; i < 4; ++i) {
            int item = tid + i*256;
            int pk = item >> 6, n4 = item & 63;
            int tile = (pk >> 3)*32 + (n4 >> 1);
            int r    = (pk >> 2) & 1;
            uint32_t base = tile*BTW + r + (pk & 3)*2;
            int lj = (n4 & 1)*4;
            #pragma unroll
            for (int j = 0; j < 4; ++j)
                Bc[base + (lj + j)*8] = pb[i][j];
        }
        __syncthreads();
        if (t + 1 < NCH) prefetch(t + 1);   // overlap global loads with mma

        #pragma unroll
        for (int kb2 = 0; kb2 < 2; ++kb2) {   // two k16 steps
            uint32_t a[2][4];
            #pragma unroll
            for (int mt = 0; mt < 2; ++mt) {
                int tile = kb2*4 + wm*2 + mt;
                uint4 av = *(const uint4*)&Ac[tile*ATW + lane*4];
                a[mt][0] = av.x; a[mt][1] = av.y;
                a[mt][2] = av.z; a[mt][3] = av.w;
            }
            #pragma unroll
            for (int nt = 0; nt < 8; ++nt) {
                int tile = kb2*32 + wn*8 + nt;
                uint2 bv = *(const uint2*)&Bc[tile*BTW + lane*2];
                #pragma unroll
                for (int mt = 0; mt < 2; ++mt) {
                    asm volatile(
                        "mma.sync.aligned.m16n8k16.row.col.f32.f16.f16.f32 "
                        "{%0,%1,%2,%3}, {%4,%5,%6,%7}, {%8,%9}, {%0,%1,%2,%3};\n"
                        : "+f"(acc[mt][nt][0]), "+f"(acc[mt][nt][1]),
                          "+f"(acc[mt][nt][2]), "+f"(acc[mt][nt][3])
                        : "r"(a[mt][0]), "r"(a[mt][1]),
                          "r"(a[mt][2]), "r"(a[mt][3]),
                          "r"(bv.x), "r"(bv.y));
                }
            }
        }
        cur ^= 1;
    }

    const int g = lane >> 2, tg = lane & 3;

    // epilogue: write raw (pre-BN) result
    #pragma unroll
    for (int mt = 0; mt < 2; ++mt) {
        int row0 = vbase + wm*32 + mt*16 + g;
        #pragma unroll
        for (int nt = 0; nt < 8; ++nt) {
            int col = wn*64 + nt*8 + tg*2;
            float2* p0 = (float2*)&out[((long)b*V_ + row0    )*FOUT_ + col];
            float2* p1 = (float2*)&out[((long)b*V_ + row0 + 8)*FOUT_ + col];
            *p0 = make_float2(acc[mt][nt][0], acc[mt][nt][1]);
            *p1 = make_float2(acc[mt][nt][2], acc[mt][nt][3]);
        }
    }

    // fused BN stats: per-column sum / sumsq over this block's 64 rows
    #pragma unroll
    for (int nt = 0; nt < 8; ++nt) {
        float s0 = acc[0][nt][0] + acc[0][nt][2] + acc[1][nt][0] + acc[1][nt][2];
        float s1 = acc[0][nt][1] + acc[0][nt][3] + acc[1][nt][1] + acc[1][nt][3];
        float q0 = acc[0][nt][0]*acc[0][nt][0] + acc[0][nt][2]*acc[0][nt][2]
                 + acc[1][nt][0]*acc[1][nt][0] + acc[1][nt][2]*acc[1][nt][2];
        float q1 = acc[0][nt][1]*acc[0][nt][1] + acc[0][nt][3]*acc[0][nt][3]
                 + acc[1][nt][1]*acc[1][nt][1] + acc[1][nt][3]*acc[1][nt][3];
        #pragma unroll
        for (int m = 4; m <= 16; m <<= 1) {
            s0 += __shfl_xor_sync(0xffffffffu, s0, m);
            s1 += __shfl_xor_sync(0xffffffffu, s1, m);
            q0 += __shfl_xor_sync(0xffffffffu, q0, m);
            q1 += __shfl_xor_sync(0xffffffffu, q1, m);
        }
        if (lane < 4) {
            int colr = wn*64 + nt*8 + tg*2;
            atomicAdd(&s_s[colr  ], s0); atomicAdd(&s_q[colr  ], q0);
            atomicAdd(&s_s[colr+1], s1); atomicAdd(&s_q[colr+1], q1);
        }
    }
    __syncthreads();
    atomicAdd(&g_sum[tid], s_s[tid]);
    atomicAdd(&g_sq[tid],  s_q[tid]);
}

// ---------------- BatchNorm finalize + apply + ReLU -------------------------
__global__ void k_bnfinal(const float* __restrict__ gamma,
                          const float* __restrict__ beta) {
    int o = threadIdx.x;
    const float n = (float)ROWS_;
    float mean = g_sum[o] / n;
    float var  = g_sq[o] / n - mean*mean;      // biased variance (torch-style)
    float sc   = gamma[o] * rsqrtf(var + 1e-5f);
    g_scale[o] = sc;
    g_shift[o] = beta[o] - mean*sc;
    g_sum[o] = 0.f;                 // self-clean for next call
    g_sq[o]  = 0.f;
}

__global__ __launch_bounds__(256) void k_bnapply(float* __restrict__ out) {
    long i = ((long)blockIdx.x*blockDim.x + threadIdx.x) * 4;
    float4 v = *(float4*)(out + i);
    int o = (int)(i & 255);
    v.x = fmaxf(fmaf(v.x, g_scale[o  ], g_shift[o  ]), 0.f);
    v.y = fmaxf(fmaf(v.y, g_scale[o+1], g_shift[o+1]), 0.f);
    v.z = fmaxf(fmaf(v.z, g_scale[o+2], g_shift[o+2]), 0.f);
    v.w = fmaxf(fmaf(v.w, g_scale[o+3], g_shift[o+3]), 0.f);
    *(float4*)(out + i) = v;
}

// ---------------- launch -----------------------------------------------------
extern "C" void kernel_launch(void* const* d_in, const int* in_sizes, int n_in,
                              void* d_out, int out_size) {
    const float* x     = (const float*)d_in[0];
    const float* ew    = (const float*)d_in[1];
    const float* w     = (const float*)d_in[2];
    const float* bias  = (const float*)d_in[3]; (void)bias; // cancels under BN
    const float* gamma = (const float*)d_in[4];
    const float* beta  = (const float*)d_in[5];
    const int*   esrc  = (const int*)d_in[6];
    const int*   edst  = (const int*)d_in[7];
    float* out = (float*)d_out;
    (void)in_sizes; (void)n_in; (void)out_size;

    // CSR build (g_cnt zero by static init + self-clean)
    k_hist<<<E_/256, 256>>>(edst);
    k_scan<<<1, 1024>>>();
    k_scatter<<<E_/256, 256>>>(esrc, edst, ew);

    // Chebyshev recursion (batch-halved for L2 residency)
    dim3 gs(V_, 2);
    k_spmm<<<gs, 256>>>(x, 1);
    k_spmm<<<gs, 256>>>(x, 2);
    k_spmm<<<gs, 256>>>(x, 3);

    // FP16 tensor-core GEMM -> raw output + fused BN statistics
    dim3 gg(V_/BM, B_);
    k_gemm<<<gg, 256>>>(x, w, out);

    // BatchNorm finalize + apply + ReLU
    k_bnfinal<<<1, FOUT_>>>(gamma, beta);
    k_bnapply<<<(ROWS_*FOUT_)/4/256, 256>>>(out);
}

// round 12
// speedup vs baseline: 1.2176x; 1.0862x over previous
#include <cuda_runtime.h>
#include <cuda_fp16.h>
#include <cstdint>

// Problem constants (fixed by the dataset)
#define B_    8
#define V_    12288
#define E_    98304
#define FIN_  256
#define FOUT_ 256
#define KCH_  4
#define BF_   (B_*FIN_)    // 2048 values per node row
#define ROWS_ (B_*V_)      // 98304 output rows

// ---------------- scratch (device globals: no runtime allocation) ----------
// Self-cleaning invariant: g_cnt, g_sum, g_sq are zero at module load and are
// returned to zero by the end of every kernel_launch call.
// Chebyshev terms stored as fp16: the GEMM rounds A to fp16 anyway, so GEMM
// numerics are unchanged; only the recursion consumes rounded T's.
__device__ __half g_Xh[(size_t)B_*V_*FIN_];   // fp16 copy of x
__device__ __half g_T1h[(size_t)V_*BF_];
__device__ __half g_T2h[(size_t)V_*BF_];
__device__ __half g_T3h[(size_t)V_*BF_];
__device__ int   g_rowptr[V_+1];
__device__ int   g_cursor[V_];
__device__ int   g_cnt[V_];
__device__ int   g_col[E_];
__device__ float g_w[E_];
__device__ float g_sum[FOUT_], g_sq[FOUT_];
__device__ float g_scale[FOUT_], g_shift[FOUT_];

__device__ __forceinline__ uint32_t h2u(__half2 h) {
    return *reinterpret_cast<uint32_t*>(&h);
}

// ---------------- x -> fp16 copy --------------------------------------------
__global__ __launch_bounds__(256) void k_xh(const float* __restrict__ x) {
    long i = ((long)blockIdx.x*256 + threadIdx.x) * 8;
    float4 a = *(const float4*)(x + i);
    float4 b = *(const float4*)(x + i + 4);
    uint4 o;
    o.x = h2u(__floats2half2_rn(a.x, a.y));
    o.y = h2u(__floats2half2_rn(a.z, a.w));
    o.z = h2u(__floats2half2_rn(b.x, b.y));
    o.w = h2u(__floats2half2_rn(b.z, b.w));
    *(uint4*)(g_Xh + i) = o;
}

// ---------------- CSR build (R6-proven) --------------------------------------
__global__ void k_hist(const int* __restrict__ dst) {
    int e = blockIdx.x*blockDim.x + threadIdx.x;
    if (e < E_) atomicAdd(&g_cnt[dst[e]], 1);
}

__global__ void k_scan() {
    __shared__ int sh[1024];
    int t = threadIdx.x;
    int base = t*12;
    int loc[12];
    int s = 0;
    #pragma unroll
    for (int i = 0; i < 12; ++i) { loc[i] = s; s += g_cnt[base+i]; }
    sh[t] = s;
    __syncthreads();
    for (int off = 1; off < 1024; off <<= 1) {
        int v = 0;
        if (t >= off) v = sh[t-off];
        __syncthreads();
        if (t >= off) sh[t] += v;
        __syncthreads();
    }
    int pre = (t == 0) ? 0 : sh[t-1];
    #pragma unroll
    for (int i = 0; i < 12; ++i) {
        int p = pre + loc[i];
        g_rowptr[base+i] = p;
        g_cursor[base+i] = p;
    }
    if (t == 1023) g_rowptr[V_] = sh[1023];
}

__global__ void k_scatter(const int* __restrict__ src, const int* __restrict__ dst,
                          const float* __restrict__ ew) {
    int e = blockIdx.x*blockDim.x + threadIdx.x;
    if (e < E_) {
        int d = dst[e];
        int p = atomicAdd(&g_cursor[d], 1);
        g_col[p] = src[e];
        g_w[p]   = ew[e];
        atomicSub(&g_cnt[d], 1);   // self-clean for next call
    }
}

// ---------------- SpMM: Chebyshev recursion (fp16 storage, f32 accumulate) --
__global__ __launch_bounds__(256) void k_spmm(int stage) {
    const __half* y;  const __half* p2 = nullptr;  __half* o;
    long ys, ps = 0;
    const int v  = blockIdx.x;
    const int j0 = (blockIdx.y << 10) + threadIdx.x*4;   // 4 halves per thread
    const long xo = (long)(j0>>8)*((long)V_*FIN_) + (j0&255);
    long yo, po = 0;
    if (stage == 1)      { y = g_Xh;  ys = FIN_; yo = xo; o = g_T1h; }
    else if (stage == 2) { y = g_T1h; ys = BF_;  yo = j0;
                           p2 = g_Xh;  ps = FIN_; po = xo; o = g_T2h; }
    else                 { y = g_T2h; ys = BF_;  yo = j0;
                           p2 = g_T1h; ps = BF_;  po = j0; o = g_T3h; }

    int r0 = g_rowptr[v], r1 = g_rowptr[v+1];
    float2 a01 = make_float2(0.f, 0.f), a23 = make_float2(0.f, 0.f);

    int e = r0;
    #pragma unroll 1
    for (; e + 4 <= r1; e += 4) {
        int   s0 = __ldg(&g_col[e]),   s1 = __ldg(&g_col[e+1]);
        int   s2 = __ldg(&g_col[e+2]), s3 = __ldg(&g_col[e+3]);
        float w0 = __ldg(&g_w[e]),     w1 = __ldg(&g_w[e+1]);
        float w2 = __ldg(&g_w[e+2]),   w3 = __ldg(&g_w[e+3]);
        uint2 t0 = *(const uint2*)(y + yo + (long)s0*ys);
        uint2 t1 = *(const uint2*)(y + yo + (long)s1*ys);
        uint2 t2 = *(const uint2*)(y + yo + (long)s2*ys);
        uint2 t3 = *(const uint2*)(y + yo + (long)s3*ys);
        float2 f;
        f = __half22float2(*(__half2*)&t0.x); a01.x = fmaf(w0,f.x,a01.x); a01.y = fmaf(w0,f.y,a01.y);
        f = __half22float2(*(__half2*)&t0.y); a23.x = fmaf(w0,f.x,a23.x); a23.y = fmaf(w0,f.y,a23.y);
        f = __half22float2(*(__half2*)&t1.x); a01.x = fmaf(w1,f.x,a01.x); a01.y = fmaf(w1,f.y,a01.y);
        f = __half22float2(*(__half2*)&t1.y); a23.x = fmaf(w1,f.x,a23.x); a23.y = fmaf(w1,f.y,a23.y);
        f = __half22float2(*(__half2*)&t2.x); a01.x = fmaf(w2,f.x,a01.x); a01.y = fmaf(w2,f.y,a01.y);
        f = __half22float2(*(__half2*)&t2.y); a23.x = fmaf(w2,f.x,a23.x); a23.y = fmaf(w2,f.y,a23.y);
        f = __half22float2(*(__half2*)&t3.x); a01.x = fmaf(w3,f.x,a01.x); a01.y = fmaf(w3,f.y,a01.y);
        f = __half22float2(*(__half2*)&t3.y); a23.x = fmaf(w3,f.x,a23.x); a23.y = fmaf(w3,f.y,a23.y);
    }
    #pragma unroll 1
    for (; e < r1; ++e) {
        int   s0 = __ldg(&g_col[e]);
        float w0 = __ldg(&g_w[e]);
        uint2 t0 = *(const uint2*)(y + yo + (long)s0*ys);
        float2 f;
        f = __half22float2(*(__half2*)&t0.x); a01.x = fmaf(w0,f.x,a01.x); a01.y = fmaf(w0,f.y,a01.y);
        f = __half22float2(*(__half2*)&t0.y); a23.x = fmaf(w0,f.x,a23.x); a23.y = fmaf(w0,f.y,a23.y);
    }
    if (p2) {
        uint2 t0 = *(const uint2*)(p2 + po + (long)v*ps);
        float2 f;
        f = __half22float2(*(__half2*)&t0.x);
        a01.x = 2.f*a01.x - f.x; a01.y = 2.f*a01.y - f.y;
        f = __half22float2(*(__half2*)&t0.y);
        a23.x = 2.f*a23.x - f.x; a23.y = 2.f*a23.y - f.y;
    }
    uint2 r;
    r.x = h2u(__floats2half2_rn(a01.x, a01.y));
    r.y = h2u(__floats2half2_rn(a23.x, a23.y));
    *(uint2*)(o + (long)v*BF_ + j0) = r;
}

// ---------------- FP16 tensor-core GEMM (m16n8k16, fragment-order smem) -----
// out[b,v,o] = sum_p sum_i A_p(v,b,i) * W[p,i,o]
// A already fp16 in memory (g_Xh/g_T1h..): prefetch is a raw copy.
// 256 threads, BM=64, BN=256 (A read from HBM exactly once), BK=32,
// double-buffered, fragment-order smem (R11-proven).
// Bias omitted: constant per-channel shift cancels through BN mean subtraction.
#define BM 64
#define BN 256
#define BK 32
#define NCH (KCH_ * FIN_ / BK)   // 32 chunks

#define ATW 132
#define BTW 66
#define ATILES 8
#define BTILES 64

__global__ __launch_bounds__(256) void k_gemm(const float* __restrict__ w,
                                              float* __restrict__ out) {
    __shared__ uint32_t As[2][ATILES*ATW];    //  8448 B
    __shared__ uint32_t Bs[2][BTILES*BTW];    // 33792 B
    __shared__ float s_s[BN], s_q[BN];        //  2048 B

    const int b     = blockIdx.y;
    const int vbase = blockIdx.x * BM;
    const int tid  = threadIdx.x;
    const int lane = tid & 31, warp = tid >> 5;
    const int wm = warp & 1, wn = warp >> 1;   // 2 warps along M, 4 along N

    s_s[tid] = 0.f; s_q[tid] = 0.f;

    float acc[2][8][4];
    #pragma unroll
    for (int i = 0; i < 2; ++i)
        #pragma unroll
        for (int j = 0; j < 8; ++j)
            #pragma unroll
            for (int c = 0; c < 4; ++c) acc[i][j][c] = 0.f;

    uint32_t pa[2][2];      // 2 A items x (kp=2q, kp=2q+1) — raw fp16 copy
    uint32_t pb[4][4];      // 4 B items x 4 cols

    auto prefetch = [&](int t) {
        const int p  = t >> 3;
        const int kb = (t & 7) * BK;
        const __half* ab; long as_;
        if (p == 0)      { ab = g_Xh  + (long)b*V_*FIN_; as_ = FIN_; }
        else if (p == 1) { ab = g_T1h + (long)b*FIN_;    as_ = BF_;  }
        else if (p == 2) { ab = g_T2h + (long)b*FIN_;    as_ = BF_;  }
        else             { ab = g_T3h + (long)b*FIN_;    as_ = BF_;  }
        #pragma unroll
        for (int i = 0; i < 2; ++i) {
            int item = tid + i*256;            // 0..511
            int row = item >> 3, q = item & 7;
            uint2 v = *(const uint2*)(ab + (long)(vbase+row)*as_ + kb + q*4);
            pa[i][0] = v.x;
            pa[i][1] = v.y;
        }
        const float* wb = w + (long)p*FIN_*FOUT_ + (long)kb*FOUT_;
        #pragma unroll
        for (int i = 0; i < 4; ++i) {
            int item = tid + i*256;            // 0..1023
            int pk = item >> 6, n4 = item & 63;
            float4 v0 = *(const float4*)(wb + (long)(2*pk  )*FOUT_ + n4*4);
            float4 v1 = *(const float4*)(wb + (long)(2*pk+1)*FOUT_ + n4*4);
            pb[i][0] = h2u(__floats2half2_rn(v0.x, v1.x));
            pb[i][1] = h2u(__floats2half2_rn(v0.y, v1.y));
            pb[i][2] = h2u(__floats2half2_rn(v0.z, v1.z));
            pb[i][3] = h2u(__floats2half2_rn(v0.w, v1.w));
        }
    };

    prefetch(0);
    int cur = 0;
    #pragma unroll 1
    for (int t = 0; t < NCH; ++t) {
        uint32_t* Ac = As[cur];
        uint32_t* Bc = Bs[cur];
        #pragma unroll
        for (int i = 0; i < 2; ++i) {
            int item = tid + i*256;
            int row = item >> 3, q = item & 7;
            int tile = (q >> 2)*4 + (row >> 4);
            int ls   = (row & 7)*4 + (q & 1)*2;
            int r4   = ((q >> 1) & 1)*2 + ((row >> 3) & 1);
            uint32_t base = tile*ATW + r4;
            Ac[base + (ls  )*4] = pa[i][0];
            Ac[base + (ls+1)*4] = pa[i][1];
        }
        #pragma unroll
        for (int i = 0; i < 4; ++i) {
            int item = tid + i*256;
            int pk = item >> 6, n4 = item & 63;
            int tile = (pk >> 3)*32 + (n4 >> 1);
            int r    = (pk >> 2) & 1;
            uint32_t base = tile*BTW + r + (pk & 3)*2;
            int lj = (n4 & 1)*4;
            #pragma unroll
            for (int j = 0; j < 4; ++j)
                Bc[base + (lj + j)*8] = pb[i][j];
        }
        __syncthreads();
        if (t + 1 < NCH) prefetch(t + 1);   // overlap global loads with mma

        #pragma unroll
        for (int kb2 = 0; kb2 < 2; ++kb2) {   // two k16 steps
            uint32_t a[2][4];
            #pragma unroll
            for (int mt = 0; mt < 2; ++mt) {
                int tile = kb2*4 + wm*2 + mt;
                uint4 av = *(const uint4*)&Ac[tile*ATW + lane*4];
                a[mt][0] = av.x; a[mt][1] = av.y;
                a[mt][2] = av.z; a[mt][3] = av.w;
            }
            #pragma unroll
            for (int nt = 0; nt < 8; ++nt) {
                int tile = kb2*32 + wn*8 + nt;
                uint2 bv = *(const uint2*)&Bc[tile*BTW + lane*2];
                #pragma unroll
                for (int mt = 0; mt < 2; ++mt) {
                    asm volatile(
                        "mma.sync.aligned.m16n8k16.row.col.f32.f16.f16.f32 "
                        "{%0,%1,%2,%3}, {%4,%5,%6,%7}, {%8,%9}, {%0,%1,%2,%3};\n"
                        : "+f"(acc[mt][nt][0]), "+f"(acc[mt][nt][1]),
                          "+f"(acc[mt][nt][2]), "+f"(acc[mt][nt][3])
                        : "r"(a[mt][0]), "r"(a[mt][1]),
                          "r"(a[mt][2]), "r"(a[mt][3]),
                          "r"(bv.x), "r"(bv.y));
                }
            }
        }
        cur ^= 1;
    }

    const int g = lane >> 2, tg = lane & 3;

    // epilogue: write raw (pre-BN) result
    #pragma unroll
    for (int mt = 0; mt < 2; ++mt) {
        int row0 = vbase + wm*32 + mt*16 + g;
        #pragma unroll
        for (int nt = 0; nt < 8; ++nt) {
            int col = wn*64 + nt*8 + tg*2;
            float2* p0 = (float2*)&out[((long)b*V_ + row0    )*FOUT_ + col];
            float2* p1 = (float2*)&out[((long)b*V_ + row0 + 8)*FOUT_ + col];
            *p0 = make_float2(acc[mt][nt][0], acc[mt][nt][1]);
            *p1 = make_float2(acc[mt][nt][2], acc[mt][nt][3]);
        }
    }

    // fused BN stats: per-column sum / sumsq over this block's 64 rows
    #pragma unroll
    for (int nt = 0; nt < 8; ++nt) {
        float s0 = acc[0][nt][0] + acc[0][nt][2] + acc[1][nt][0] + acc[1][nt][2];
        float s1 = acc[0][nt][1] + acc[0][nt][3] + acc[1][nt][1] + acc[1][nt][3];
        float q0 = acc[0][nt][0]*acc[0][nt][0] + acc[0][nt][2]*acc[0][nt][2]
                 + acc[1][nt][0]*acc[1][nt][0] + acc[1][nt][2]*acc[1][nt][2];
        float q1 = acc[0][nt][1]*acc[0][nt][1] + acc[0][nt][3]*acc[0][nt][3]
                 + acc[1][nt][1]*acc[1][nt][1] + acc[1][nt][3]*acc[1][nt][3];
        #pragma unroll
        for (int m = 4; m <= 16; m <<= 1) {
            s0 += __shfl_xor_sync(0xffffffffu, s0, m);
            s1 += __shfl_xor_sync(0xffffffffu, s1, m);
            q0 += __shfl_xor_sync(0xffffffffu, q0, m);
            q1 += __shfl_xor_sync(0xffffffffu, q1, m);
        }
        if (lane < 4) {
            int colr = wn*64 + nt*8 + tg*2;
            atomicAdd(&s_s[colr  ], s0); atomicAdd(&s_q[colr  ], q0);
            atomicAdd(&s_s[colr+1], s1); atomicAdd(&s_q[colr+1], q1);
        }
    }
    __syncthreads();
    atomicAdd(&g_sum[tid], s_s[tid]);
    atomicAdd(&g_sq[tid],  s_q[tid]);
}

// ---------------- BatchNorm finalize + apply + ReLU -------------------------
__global__ void k_bnfinal(const float* __restrict__ gamma,
                          const float* __restrict__ beta) {
    int o = threadIdx.x;
    const float n = (float)ROWS_;
    float mean = g_sum[o] / n;
    float var  = g_sq[o] / n - mean*mean;      // biased variance (torch-style)
    float sc   = gamma[o] * rsqrtf(var + 1e-5f);
    g_scale[o] = sc;
    g_shift[o] = beta[o] - mean*sc;
    g_sum[o] = 0.f;                 // self-clean for next call
    g_sq[o]  = 0.f;
}

__global__ __launch_bounds__(256) void k_bnapply(float* __restrict__ out) {
    long i = ((long)blockIdx.x*blockDim.x + threadIdx.x) * 4;
    float4 v = *(float4*)(out + i);
    int o = (int)(i & 255);
    v.x = fmaxf(fmaf(v.x, g_scale[o  ], g_shift[o  ]), 0.f);
    v.y = fmaxf(fmaf(v.y, g_scale[o+1], g_shift[o+1]), 0.f);
    v.z = fmaxf(fmaf(v.z, g_scale[o+2], g_shift[o+2]), 0.f);
    v.w = fmaxf(fmaf(v.w, g_scale[o+3], g_shift[o+3]), 0.f);
    *(float4*)(out + i) = v;
}

// ---------------- launch -----------------------------------------------------
extern "C" void kernel_launch(void* const* d_in, const int* in_sizes, int n_in,
                              void* d_out, int out_size) {
    const float* x     = (const float*)d_in[0];
    const float* ew    = (const float*)d_in[1];
    const float* w     = (const float*)d_in[2];
    const float* bias  = (const float*)d_in[3]; (void)bias; // cancels under BN
    const float* gamma = (const float*)d_in[4];
    const float* beta  = (const float*)d_in[5];
    const int*   esrc  = (const int*)d_in[6];
    const int*   edst  = (const int*)d_in[7];
    float* out = (float*)d_out;
    (void)in_sizes; (void)n_in; (void)out_size;

    // x -> fp16 copy (independent of CSR)
    k_xh<<<(B_*V_*FIN_)/(256*8), 256>>>(x);

    // CSR build (g_cnt zero by static init + self-clean)
    k_hist<<<E_/256, 256>>>(edst);
    k_scan<<<1, 1024>>>();
    k_scatter<<<E_/256, 256>>>(esrc, edst, ew);

    // Chebyshev recursion (fp16 storage, f32 accumulate; batch-halved grid)
    dim3 gs(V_, 2);
    k_spmm<<<gs, 256>>>(1);
    k_spmm<<<gs, 256>>>(2);
    k_spmm<<<gs, 256>>>(3);

    // FP16 tensor-core GEMM -> raw output + fused BN statistics
    dim3 gg(V_/BM, B_);
    k_gemm<<<gg, 256>>>(w, out);

    // BatchNorm finalize + apply + ReLU
    k_bnfinal<<<1, FOUT_>>>(gamma, beta);
    k_bnapply<<<(ROWS_*FOUT_)/4/256, 256>>>(out);
}

// round 13
// speedup vs baseline: 1.2808x; 1.0519x over previous
#include <cuda_runtime.h>
#include <cuda_fp16.h>
#include <cstdint>

// Problem constants (fixed by the dataset)
#define B_    8
#define V_    12288
#define E_    98304
#define FIN_  256
#define FOUT_ 256
#define KCH_  4
#define BF_   (B_*FIN_)    // 2048 values per node row
#define ROWS_ (B_*V_)      // 98304 output rows

// ---------------- scratch (device globals: no runtime allocation) ----------
// Self-cleaning invariant: g_cnt, g_sum, g_sq are zero at module load and are
// returned to zero within every kernel_launch call (k_xh re-zeroes g_cnt
// before k_hist; k_bnfinal re-zeroes g_sum/g_sq).
__device__ __half g_Xh[(size_t)B_*V_*FIN_];   // fp16 copy of x
__device__ __half g_T1h[(size_t)V_*BF_];
__device__ __half g_T2h[(size_t)V_*BF_];
__device__ __half g_T3h[(size_t)V_*BF_];
__device__ __half g_Wh[(size_t)KCH_*FIN_*FOUT_];  // fp16 W, k-pair interleaved
__device__ int   g_rowptr[V_+1];
__device__ int   g_cursor[V_];
__device__ int   g_cnt[V_];
__device__ int   g_col[E_];
__device__ float g_w[E_];
__device__ float g_sum[FOUT_], g_sq[FOUT_];
__device__ float g_scale[FOUT_], g_shift[FOUT_];

__device__ __forceinline__ uint32_t h2u(__half2 h) {
    return *reinterpret_cast<uint32_t*>(&h);
}

// ---------------- x -> fp16 copy (+ zero g_cnt for the CSR hist) ------------
__global__ __launch_bounds__(256) void k_xh(const float* __restrict__ x) {
    long gi = (long)blockIdx.x*256 + threadIdx.x;
    if (gi < V_) g_cnt[gi] = 0;          // runs before k_hist in stream order
    long i = gi * 8;
    float4 a = *(const float4*)(x + i);
    float4 b = *(const float4*)(x + i + 4);
    uint4 o;
    o.x = h2u(__floats2half2_rn(a.x, a.y));
    o.y = h2u(__floats2half2_rn(a.z, a.w));
    o.z = h2u(__floats2half2_rn(b.x, b.y));
    o.w = h2u(__floats2half2_rn(b.z, b.w));
    *(uint4*)(g_Xh + i) = o;
}

// ---------------- w -> fp16, k-pair interleaved ------------------------------
// Word (uint32) at g_Wh[((p*128 + pk)*256 + n)*2 halves] packs
// (w[p][2pk][n], w[p][2pk+1][n]) — exactly the B mma fragment for (n, pk).
__global__ __launch_bounds__(256) void k_wh(const float* __restrict__ w) {
    int p  = blockIdx.x >> 7;            // 4 p-values
    int pk = blockIdx.x & 127;           // 128 k-pairs
    int n  = threadIdx.x;                // 256 columns
    const float* wp = w + (long)p*FIN_*FOUT_;
    float v0 = wp[(long)(2*pk  )*FOUT_ + n];
    float v1 = wp[(long)(2*pk+1)*FOUT_ + n];
    *(uint32_t*)(g_Wh + (((long)p*128 + pk)*FOUT_ + n)*2) =
        h2u(__floats2half2_rn(v0, v1));
}

// ---------------- CSR build (g_cnt zeroed by k_xh) ---------------------------
__global__ void k_hist(const int* __restrict__ dst) {
    int e = blockIdx.x*blockDim.x + threadIdx.x;
    if (e < E_) atomicAdd(&g_cnt[dst[e]], 1);
}

__global__ void k_scan() {
    __shared__ int sh[1024];
    int t = threadIdx.x;
    int base = t*12;
    int loc[12];
    int s = 0;
    #pragma unroll
    for (int i = 0; i < 12; ++i) { loc[i] = s; s += g_cnt[base+i]; }
    sh[t] = s;
    __syncthreads();
    for (int off = 1; off < 1024; off <<= 1) {
        int v = 0;
        if (t >= off) v = sh[t-off];
        __syncthreads();
        if (t >= off) sh[t] += v;
        __syncthreads();
    }
    int pre = (t == 0) ? 0 : sh[t-1];
    #pragma unroll
    for (int i = 0; i < 12; ++i) {
        int p = pre + loc[i];
        g_rowptr[base+i] = p;
        g_cursor[base+i] = p;
    }
    if (t == 1023) g_rowptr[V_] = sh[1023];
}

__global__ void k_scatter(const int* __restrict__ src, const int* __restrict__ dst,
                          const float* __restrict__ ew) {
    int e = blockIdx.x*blockDim.x + threadIdx.x;
    if (e < E_) {
        int d = dst[e];
        int p = atomicAdd(&g_cursor[d], 1);
        g_col[p] = src[e];
        g_w[p]   = ew[e];
    }
}

// ---------------- SpMM: Chebyshev recursion (fp16 storage, f32 accumulate) --
__global__ __launch_bounds__(256) void k_spmm(int stage) {
    const __half* y;  const __half* p2 = nullptr;  __half* o;
    long ys, ps = 0;
    const int v  = blockIdx.x;
    const int j0 = (blockIdx.y << 10) + threadIdx.x*4;   // 4 halves per thread
    const long xo = (long)(j0>>8)*((long)V_*FIN_) + (j0&255);
    long yo, po = 0;
    if (stage == 1)      { y = g_Xh;  ys = FIN_; yo = xo; o = g_T1h; }
    else if (stage == 2) { y = g_T1h; ys = BF_;  yo = j0;
                           p2 = g_Xh;  ps = FIN_; po = xo; o = g_T2h; }
    else                 { y = g_T2h; ys = BF_;  yo = j0;
                           p2 = g_T1h; ps = BF_;  po = j0; o = g_T3h; }

    int r0 = g_rowptr[v], r1 = g_rowptr[v+1];
    float2 a01 = make_float2(0.f, 0.f), a23 = make_float2(0.f, 0.f);

    int e = r0;
    #pragma unroll 1
    for (; e + 4 <= r1; e += 4) {
        int   s0 = __ldg(&g_col[e]),   s1 = __ldg(&g_col[e+1]);
        int   s2 = __ldg(&g_col[e+2]), s3 = __ldg(&g_col[e+3]);
        float w0 = __ldg(&g_w[e]),     w1 = __ldg(&g_w[e+1]);
        float w2 = __ldg(&g_w[e+2]),   w3 = __ldg(&g_w[e+3]);
        uint2 t0 = *(const uint2*)(y + yo + (long)s0*ys);
        uint2 t1 = *(const uint2*)(y + yo + (long)s1*ys);
        uint2 t2 = *(const uint2*)(y + yo + (long)s2*ys);
        uint2 t3 = *(const uint2*)(y + yo + (long)s3*ys);
        float2 f;
        f = __half22float2(*(__half2*)&t0.x); a01.x = fmaf(w0,f.x,a01.x); a01.y = fmaf(w0,f.y,a01.y);
        f = __half22float2(*(__half2*)&t0.y); a23.x = fmaf(w0,f.x,a23.x); a23.y = fmaf(w0,f.y,a23.y);
        f = __half22float2(*(__half2*)&t1.x); a01.x = fmaf(w1,f.x,a01.x); a01.y = fmaf(w1,f.y,a01.y);
        f = __half22float2(*(__half2*)&t1.y); a23.x = fmaf(w1,f.x,a23.x); a23.y = fmaf(w1,f.y,a23.y);
        f = __half22float2(*(__half2*)&t2.x); a01.x = fmaf(w2,f.x,a01.x); a01.y = fmaf(w2,f.y,a01.y);
        f = __half22float2(*(__half2*)&t2.y); a23.x = fmaf(w2,f.x,a23.x); a23.y = fmaf(w2,f.y,a23.y);
        f = __half22float2(*(__half2*)&t3.x); a01.x = fmaf(w3,f.x,a01.x); a01.y = fmaf(w3,f.y,a01.y);
        f = __half22float2(*(__half2*)&t3.y); a23.x = fmaf(w3,f.x,a23.x); a23.y = fmaf(w3,f.y,a23.y);
    }
    #pragma unroll 1
    for (; e < r1; ++e) {
        int   s0 = __ldg(&g_col[e]);
        float w0 = __ldg(&g_w[e]);
        uint2 t0 = *(const uint2*)(y + yo + (long)s0*ys);
        float2 f;
        f = __half22float2(*(__half2*)&t0.x); a01.x = fmaf(w0,f.x,a01.x); a01.y = fmaf(w0,f.y,a01.y);
        f = __half22float2(*(__half2*)&t0.y); a23.x = fmaf(w0,f.x,a23.x); a23.y = fmaf(w0,f.y,a23.y);
    }
    if (p2) {
        uint2 t0 = *(const uint2*)(p2 + po + (long)v*ps);
        float2 f;
        f = __half22float2(*(__half2*)&t0.x);
        a01.x = 2.f*a01.x - f.x; a01.y = 2.f*a01.y - f.y;
        f = __half22float2(*(__half2*)&t0.y);
        a23.x = 2.f*a23.x - f.x; a23.y = 2.f*a23.y - f.y;
    }
    uint2 r;
    r.x = h2u(__floats2half2_rn(a01.x, a01.y));
    r.y = h2u(__floats2half2_rn(a23.x, a23.y));
    *(uint2*)(o + (long)v*BF_ + j0) = r;
}

// ---------------- FP16 tensor-core GEMM (m16n8k16, fragment-order smem) -----
// out[b,v,o] = sum_p sum_i A_p(v,b,i) * W[p,i,o]
// A and W both fp16 in memory: both prefetches are raw copies.
// B item mapping: item = pk*64 + n4 (pk 0..15, n4 0..63); loads uint2 =
// words for n = 4*n4+0..3? NO — words for (n4*... ) see store below:
// g_Wh word index (p,pk,n) = (p*128+pk)*256 + n; item loads uint2 at
// word (pk, 2*n4) covering n = 2*n4, 2*n4+1. 512 items * 2 words = 1024
// words = 16 pk x 64 n2-groups... pk 0..15, n2 0..127: item = pk*... 
// Simpler: 2048 words per chunk (16 pk x 256 n/2?) -> 16*128=2048 uint2.
// 256 threads x 2 items x (1 uint4 = 4 words): item = pk*32 + n16
// covering n = 16*n16/... — see code: item -> pk = item>>5, ng = item&31,
// uint4 at word (pk, ng*8) = n = 8*ng .. 8*ng+3?? uint4 = 4 words = n 8ng..8ng+3.
// That covers only n = 0..255 step: ng*8+0..3 — misses +4..7!
// CORRECT mapping used below: 2 uint4 per item, covering n = 8*ng..8*ng+7.
#define BM 64
#define BN 256
#define BK 32
#define NCH (KCH_ * FIN_ / BK)   // 32 chunks

#define ATW 132
#define BTW 66
#define ATILES 8
#define BTILES 64

__global__ __launch_bounds__(256) void k_gemm(float* __restrict__ out) {
    __shared__ uint32_t As[2][ATILES*ATW];    //  8448 B
    __shared__ uint32_t Bs[2][BTILES*BTW];    // 33792 B
    __shared__ float s_s[BN], s_q[BN];        //  2048 B

    const int b     = blockIdx.y;
    const int vbase = blockIdx.x * BM;
    const int tid  = threadIdx.x;
    const int lane = tid & 31, warp = tid >> 5;
    const int wm = warp & 1, wn = warp >> 1;   // 2 warps along M, 4 along N

    s_s[tid] = 0.f; s_q[tid] = 0.f;

    float acc[2][8][4];
    #pragma unroll
    for (int i = 0; i < 2; ++i)
        #pragma unroll
        for (int j = 0; j < 8; ++j)
            #pragma unroll
            for (int c = 0; c < 4; ++c) acc[i][j][c] = 0.f;

    uint32_t pa[2][2];      // 2 A items — raw fp16 copy
    uint4    pb[2][2];      // item (pk, ng): n = 8*ng..8*ng+7, 2 uint4

    auto prefetch = [&](int t) {
        const int p  = t >> 3;
        const int kb = (t & 7) * BK;
        const __half* ab; long as_;
        if (p == 0)      { ab = g_Xh  + (long)b*V_*FIN_; as_ = FIN_; }
        else if (p == 1) { ab = g_T1h + (long)b*FIN_;    as_ = BF_;  }
        else if (p == 2) { ab = g_T2h + (long)b*FIN_;    as_ = BF_;  }
        else             { ab = g_T3h + (long)b*FIN_;    as_ = BF_;  }
        #pragma unroll
        for (int i = 0; i < 2; ++i) {
            int item = tid + i*256;            // 0..511
            int row = item >> 3, q = item & 7;
            uint2 v = *(const uint2*)(ab + (long)(vbase+row)*as_ + kb + q*4);
            pa[i][0] = v.x;
            pa[i][1] = v.y;
        }
        // B: 16 k-pairs (kb/2 .. kb/2+15) x 256 n, one word per (pk, n).
        // item = pk*32 + ng (512 items): loads words n = 8*ng .. 8*ng+7.
        const uint32_t* wb = (const uint32_t*)g_Wh + ((long)p*128 + (kb >> 1))*FOUT_;
        #pragma unroll
        for (int i = 0; i < 2; ++i) {
            int item = tid + i*256;
            int pk = item >> 5, ng = item & 31;
            const uint4* src = (const uint4*)(wb + (long)pk*FOUT_ + ng*8);
            pb[i][0] = src[0];
            pb[i][1] = src[1];
        }
    };

    prefetch(0);
    int cur = 0;
    #pragma unroll 1
    for (int t = 0; t < NCH; ++t) {
        uint32_t* Ac = As[cur];
        uint32_t* Bc = Bs[cur];
        #pragma unroll
        for (int i = 0; i < 2; ++i) {
            int item = tid + i*256;
            int row = item >> 3, q = item & 7;
            int tile = (q >> 2)*4 + (row >> 4);
            int ls   = (row & 7)*4 + (q & 1)*2;
            int r4   = ((q >> 1) & 1)*2 + ((row >> 3) & 1);
            uint32_t base = tile*ATW + r4;
            Ac[base + (ls  )*4] = pa[i][0];
            Ac[base + (ls+1)*4] = pa[i][1];
        }
        // B store: word (pk, n) -> tile = (pk>>3)*32 + (n>>3),
        //          lane = (n&7)*4 + (pk&3), r = (pk>>2)&1
        #pragma unroll
        for (int i = 0; i < 2; ++i) {
            int item = tid + i*256;
            int pk = item >> 5, ng = item & 31;
            int tile = (pk >> 3)*32 + ng;          // n>>3 == ng for n=8ng+j
            uint32_t base = tile*BTW + ((pk >> 2) & 1) + (pk & 3)*2;
            const uint32_t* pv0 = (const uint32_t*)&pb[i][0];
            const uint32_t* pv1 = (const uint32_t*)&pb[i][1];
            #pragma unroll
            for (int j = 0; j < 4; ++j) Bc[base + j*8]     = pv0[j];
            #pragma unroll
            for (int j = 0; j < 4; ++j) Bc[base + (j+4)*8] = pv1[j];
        }
        __syncthreads();
        if (t + 1 < NCH) prefetch(t + 1);   // overlap global loads with mma

        #pragma unroll
        for (int kb2 = 0; kb2 < 2; ++kb2) {   // two k16 steps
            uint32_t a[2][4];
            #pragma unroll
            for (int mt = 0; mt < 2; ++mt) {
                int tile = kb2*4 + wm*2 + mt;
                uint4 av = *(const uint4*)&Ac[tile*ATW + lane*4];
                a[mt][0] = av.x; a[mt][1] = av.y;
                a[mt][2] = av.z; a[mt][3] = av.w;
            }
            #pragma unroll
            for (int nt = 0; nt < 8; ++nt) {
                int tile = kb2*32 + wn*8 + nt;
                uint2 bv = *(const uint2*)&Bc[tile*BTW + lane*2];
                #pragma unroll
                for (int mt = 0; mt < 2; ++mt) {
                    asm volatile(
                        "mma.sync.aligned.m16n8k16.row.col.f32.f16.f16.f32 "
                        "{%0,%1,%2,%3}, {%4,%5,%6,%7}, {%8,%9}, {%0,%1,%2,%3};\n"
                        : "+f"(acc[mt][nt][0]), "+f"(acc[mt][nt][1]),
                          "+f"(acc[mt][nt][2]), "+f"(acc[mt][nt][3])
                        : "r"(a[mt][0]), "r"(a[mt][1]),
                          "r"(a[mt][2]), "r"(a[mt][3]),
                          "r"(bv.x), "r"(bv.y));
                }
            }
        }
        cur ^= 1;
    }

    const int g = lane >> 2, tg = lane & 3;

    // epilogue: write raw (pre-BN) result
    #pragma unroll
    for (int mt = 0; mt < 2; ++mt) {
        int row0 = vbase + wm*32 + mt*16 + g;
        #pragma unroll
        for (int nt = 0; nt < 8; ++nt) {
            int col = wn*64 + nt*8 + tg*2;
            float2* p0 = (float2*)&out[((long)b*V_ + row0    )*FOUT_ + col];
            float2* p1 = (float2*)&out[((long)b*V_ + row0 + 8)*FOUT_ + col];
            *p0 = make_float2(acc[mt][nt][0], acc[mt][nt][1]);
            *p1 = make_float2(acc[mt][nt][2], acc[mt][nt][3]);
        }
    }

    // fused BN stats: per-column sum / sumsq over this block's 64 rows
    #pragma unroll
    for (int nt = 0; nt < 8; ++nt) {
        float s0 = acc[0][nt][0] + acc[0][nt][2] + acc[1][nt][0] + acc[1][nt][2];
        float s1 = acc[0][nt][1] + acc[0][nt][3] + acc[1][nt][1] + acc[1][nt][3];
        float q0 = acc[0][nt][0]*acc[0][nt][0] + acc[0][nt][2]*acc[0][nt][2]
                 + acc[1][nt][0]*acc[1][nt][0] + acc[1][nt][2]*acc[1][nt][2];
        float q1 = acc[0][nt][1]*acc[0][nt][1] + acc[0][nt][3]*acc[0][nt][3]
                 + acc[1][nt][1]*acc[1][nt][1] + acc[1][nt][3]*acc[1][nt][3];
        #pragma unroll
        for (int m = 4; m <= 16; m <<= 1) {
            s0 += __shfl_xor_sync(0xffffffffu, s0, m);
            s1 += __shfl_xor_sync(0xffffffffu, s1, m);
            q0 += __shfl_xor_sync(0xffffffffu, q0, m);
            q1 += __shfl_xor_sync(0xffffffffu, q1, m);
        }
        if (lane < 4) {
            int colr = wn*64 + nt*8 + tg*2;
            atomicAdd(&s_s[colr  ], s0); atomicAdd(&s_q[colr  ], q0);
            atomicAdd(&s_s[colr+1], s1); atomicAdd(&s_q[colr+1], q1);
        }
    }
    __syncthreads();
    atomicAdd(&g_sum[tid], s_s[tid]);
    atomicAdd(&g_sq[tid],  s_q[tid]);
}

// ---------------- BatchNorm finalize + apply + ReLU -------------------------
__global__ void k_bnfinal(const float* __restrict__ gamma,
                          const float* __restrict__ beta) {
    int o = threadIdx.x;
    const float n = (float)ROWS_;
    float mean = g_sum[o] / n;
    float var  = g_sq[o] / n - mean*mean;      // biased variance (torch-style)
    float sc   = gamma[o] * rsqrtf(var + 1e-5f);
    g_scale[o] = sc;
    g_shift[o] = beta[o] - mean*sc;
    g_sum[o] = 0.f;                 // self-clean for next call
    g_sq[o]  = 0.f;
}

__global__ __launch_bounds__(256) void k_bnapply(float* __restrict__ out) {
    long i = ((long)blockIdx.x*blockDim.x + threadIdx.x) * 4;
    float4 v = *(float4*)(out + i);
    int o = (int)(i & 255);
    v.x = fmaxf(fmaf(v.x, g_scale[o  ], g_shift[o  ]), 0.f);
    v.y = fmaxf(fmaf(v.y, g_scale[o+1], g_shift[o+1]), 0.f);
    v.z = fmaxf(fmaf(v.z, g_scale[o+2], g_shift[o+2]), 0.f);
    v.w = fmaxf(fmaf(v.w, g_scale[o+3], g_shift[o+3]), 0.f);
    *(float4*)(out + i) = v;
}

// ---------------- launch -----------------------------------------------------
extern "C" void kernel_launch(void* const* d_in, const int* in_sizes, int n_in,
                              void* d_out, int out_size) {
    const float* x     = (const float*)d_in[0];
    const float* ew    = (const float*)d_in[1];
    const float* w     = (const float*)d_in[2];
    const float* bias  = (const float*)d_in[3]; (void)bias; // cancels under BN
    const float* gamma = (const float*)d_in[4];
    const float* beta  = (const float*)d_in[5];
    const int*   esrc  = (const int*)d_in[6];
    const int*   edst  = (const int*)d_in[7];
    float* out = (float*)d_out;
    (void)in_sizes; (void)n_in; (void)out_size;

    // fp16 conversions (k_xh also zeroes g_cnt ahead of k_hist)
    k_xh<<<(B_*V_*FIN_)/(256*8), 256>>>(x);
    k_wh<<<KCH_*128, 256>>>(w);

    // CSR build
    k_hist<<<E_/256, 256>>>(edst);
    k_scan<<<1, 1024>>>();
    k_scatter<<<E_/256, 256>>>(esrc, edst, ew);

    // Chebyshev recursion (fp16 storage, f32 accumulate; batch-halved grid)
    dim3 gs(V_, 2);
    k_spmm<<<gs, 256>>>(1);
    k_spmm<<<gs, 256>>>(2);
    k_spmm<<<gs, 256>>>(3);

    // FP16 tensor-core GEMM -> raw output + fused BN statistics
    dim3 gg(V_/BM, B_);
    k_gemm<<<gg, 256>>>(out);

    // BatchNorm finalize + apply + ReLU
    k_bnfinal<<<1, FOUT_>>>(gamma, beta);
    k_bnapply<<<(ROWS_*FOUT_)/4/256, 256>>>(out);
}